// round 13
// baseline (speedup 1.0000x reference)
#include <cuda_runtime.h>
#include <cuda_fp16.h>
#include <math.h>
#include <stdint.h>

#define N_OBJ  16384
#define N_PAIR 131072
#define DD     256

// ---------------- scratch (static device memory; no allocations) ----------------
__device__ float g_objA[(size_t)N_OBJ  * DD];
__device__ float g_predA[(size_t)N_PAIR * DD];
__device__ float g_msgO[(size_t)N_OBJ  * DD];
__device__ float g_aO1[N_OBJ];
__device__ float g_aO2[N_OBJ];
__device__ float g_pP1[N_PAIR];
__device__ float g_pP2[N_PAIR];
// half-precision MMA operand buffers
__device__ __half g_msgP_h[(size_t)N_PAIR * DD];
__device__ __half g_msgO_h[(size_t)N_OBJ  * DD];
__device__ __half g_objH_h[(size_t)N_OBJ  * DD];
__device__ __half g_predH_h[(size_t)N_PAIR * DD];
__device__ __half g_Wih_h[3 * DD * DD];
__device__ __half g_Whh_h[3 * DD * DD];

__device__ __forceinline__ float sigf(float x) { return 1.0f / (1.0f + expf(-x)); }

// ---------------- float -> half conversion (8 elems / thread) ----------------
__global__ void f2h_kernel(const float* __restrict__ src, __half* __restrict__ dst, int n8)
{
    int i = blockIdx.x * blockDim.x + threadIdx.x;
    if (i >= n8) return;
    const float4* s4 = (const float4*)src;
    float4 a = s4[2 * i];
    float4 b = s4[2 * i + 1];
    __half2 h[4];
    h[0] = __floats2half2_rn(a.x, a.y);
    h[1] = __floats2half2_rn(a.z, a.w);
    h[2] = __floats2half2_rn(b.x, b.y);
    h[3] = __floats2half2_rn(b.z, b.w);
    ((uint4*)dst)[i] = *(uint4*)h;
}

// ---------------- fused per-row gate scalars + half conversion ----------------
__global__ void rs_f2h_kernel(const float* __restrict__ X, int M,
                              const float* __restrict__ wA, const float* __restrict__ wB,
                              float* __restrict__ outA, float* __restrict__ outB,
                              __half* __restrict__ Xh)
{
    int row = (blockIdx.x * blockDim.x + threadIdx.x) >> 5;
    int lane = threadIdx.x & 31;
    if (row >= M) return;
    const float4* xr = (const float4*)(X + (size_t)row * DD);
    const float4* wa4 = (const float4*)wA;
    const float4* wb4 = (const float4*)wB;
    float sA = 0.f, sB = 0.f;
    __half2 hout[4];
#pragma unroll
    for (int h = 0; h < 2; ++h) {
        int c4 = 2 * lane + h;
        float4 v = xr[c4];
        float4 a = wa4[c4];
        float4 b = wb4[c4];
        float rx = fmaxf(v.x, 0.f), ry = fmaxf(v.y, 0.f);
        float rz = fmaxf(v.z, 0.f), rw = fmaxf(v.w, 0.f);
        sA += rx * a.x + ry * a.y + rz * a.z + rw * a.w;
        sB += rx * b.x + ry * b.y + rz * b.z + rw * b.w;
        hout[2 * h]     = __floats2half2_rn(v.x, v.y);
        hout[2 * h + 1] = __floats2half2_rn(v.z, v.w);
    }
    ((uint4*)(Xh + (size_t)row * DD))[lane] = *(uint4*)hout;
#pragma unroll
    for (int o = 16; o > 0; o >>= 1) {
        sA += __shfl_xor_sync(0xFFFFFFFFu, sA, o);
        sB += __shfl_xor_sync(0xFFFFFFFFu, sB, o);
    }
    if (lane == 0) { outA[row] = sA; outB[row] = sB; }
}

// ---------------- zero msgO ----------------
__global__ void zero_kernel(float4* __restrict__ p, int n4)
{
    int i = blockIdx.x * blockDim.x + threadIdx.x;
    if (i < n4) p[i] = make_float4(0.f, 0.f, 0.f, 0.f);
}

// ---------------- edge kernel (fp16 feature reads; msgP half out) ----------------
__global__ void edge_kernel(const __half* __restrict__ xp,   // predH_h
                            const __half* __restrict__ xo,   // objH_h
                            const int*   __restrict__ pidx,
                            const float* __restrict__ aO1, const float* __restrict__ aO2,
                            const float* __restrict__ pP1, const float* __restrict__ pP2,
                            const float* __restrict__ b_e2v, const float* __restrict__ b_v2e,
                            float* __restrict__ msgO, __half* __restrict__ msgP)
{
    int e = (blockIdx.x * blockDim.x + threadIdx.x) >> 5;
    int lane = threadIdx.x & 31;
    if (e >= N_PAIR) return;

    int s = pidx[2 * e];
    int o = pidx[2 * e + 1];
    float be = b_e2v[0];
    float bv = b_v2e[0];
    float p1 = pP1[e], p2 = pP2[e];
    float g1 = sigf(aO1[s] + p1 + be);   // m_subj = g1 * x_pred[e] -> msgO[s]
    float g2 = sigf(aO1[o] + p1 + be);   // m_obj  = g2 * x_pred[e] -> msgO[o]
    float gs = sigf(aO2[s] + p2 + bv);   // m_s2p  = gs * x_obj[s]
    float go = sigf(aO2[o] + p2 + bv);   // m_o2p  = go * x_obj[o]

    // each lane handles 8 halves = one uint4 per row
    uint4 vp = ((const uint4*)(xp + (size_t)e * DD))[lane];
    uint4 vs = ((const uint4*)(xo + (size_t)s * DD))[lane];
    uint4 vo = ((const uint4*)(xo + (size_t)o * DD))[lane];
    const __half2* vph = (const __half2*)&vp;
    const __half2* vsh = (const __half2*)&vs;
    const __half2* voh = (const __half2*)&vo;

    __half2 mpout[4];
    float a1[8], a2[8];
#pragma unroll
    for (int q = 0; q < 4; ++q) {
        float2 p  = __half22float2(vph[q]);
        float2 sv = __half22float2(vsh[q]);
        float2 ov = __half22float2(voh[q]);
        mpout[q] = __floats2half2_rn(gs * sv.x + go * ov.x, gs * sv.y + go * ov.y);
        a1[2 * q] = g1 * p.x; a1[2 * q + 1] = g1 * p.y;
        a2[2 * q] = g2 * p.x; a2[2 * q + 1] = g2 * p.y;
    }
    ((uint4*)(msgP + (size_t)e * DD))[lane] = *(uint4*)mpout;

    float4* mos = (float4*)(msgO + (size_t)s * DD);
    float4* moo = (float4*)(msgO + (size_t)o * DD);
    atomicAdd(&mos[2 * lane],     make_float4(a1[0], a1[1], a1[2], a1[3]));
    atomicAdd(&mos[2 * lane + 1], make_float4(a1[4], a1[5], a1[6], a1[7]));
    atomicAdd(&moo[2 * lane],     make_float4(a2[0], a2[1], a2[2], a2[3]));
    atomicAdd(&moo[2 * lane + 1], make_float4(a2[4], a2[5], a2[6], a2[7]));
}

// ================= fp16 mma.sync fused GRU =================
// Y = GRU(X, H). 4 accumulator groups:
//   accR = X@Wr_ih^T + H@Wr_hh^T ; accZ likewise ; accI = X@Wn_ih^T ; accN = H@Wn_hh^T
// BM=128, BN=64, BK=32 halves; 512 threads (16 warps: 4m x 4n, warp tile 32x16).
// 3-stage cp.async ring; H blend captured from the AsH staging tile at the
// stage whose k-range covers this warp's output columns.
#define TBM 128
#define TBN 64
#define TBK 32            // halves per stage
#define ROWB 80           // smem row stride bytes (40 halves)
#define NBUF 3

#define ABUF (TBM * ROWB)            // 10240 B per matrix per buffer
#define BGT  (TBN * ROWB)            // 5120 B per gate tile
#define BBUF (6 * BGT)               // 30720 B per buffer
#define OFF_AX 0
#define OFF_AH (NBUF * ABUF)         // 30720
#define OFF_B  (2 * NBUF * ABUF)     // 61440
#define GRU_SMEM (OFF_B + NBUF * BBUF)  // 153600

__device__ __forceinline__ uint32_t smem_u32(const void* p) {
    return (uint32_t)__cvta_generic_to_shared(p);
}
#define CP16(dst, src) \
    asm volatile("cp.async.cg.shared.global [%0], [%1], 16;\n" :: "r"(dst), "l"(src) : "memory")
__device__ __forceinline__ void cp_commit() {
    asm volatile("cp.async.commit_group;\n" ::: "memory");
}
template<int N> __device__ __forceinline__ void cp_wait() {
    asm volatile("cp.async.wait_group %0;\n" :: "n"(N) : "memory");
}
__device__ __forceinline__ void ldsm4(uint32_t* r, uint32_t addr) {
    asm volatile("ldmatrix.sync.aligned.m8n8.x4.shared.b16 {%0,%1,%2,%3}, [%4];\n"
        : "=r"(r[0]), "=r"(r[1]), "=r"(r[2]), "=r"(r[3]) : "r"(addr));
}
__device__ __forceinline__ void mma_f16(float* c, const uint32_t* a, const uint32_t* b) {
    asm volatile("mma.sync.aligned.m16n8k16.row.col.f32.f16.f16.f32 "
        "{%0,%1,%2,%3}, {%4,%5,%6,%7}, {%8,%9}, {%0,%1,%2,%3};\n"
        : "+f"(c[0]), "+f"(c[1]), "+f"(c[2]), "+f"(c[3])
        : "r"(a[0]), "r"(a[1]), "r"(a[2]), "r"(a[3]), "r"(b[0]), "r"(b[1]));
}

__global__ __launch_bounds__(512, 1)
void gru_fp16(const __half* __restrict__ Xh, const __half* __restrict__ Hh,
              const __half* __restrict__ Wih, const __half* __restrict__ Whh,
              const float* __restrict__ bih, const float* __restrict__ bhh,
              float* __restrict__ Y)
{
    extern __shared__ __align__(128) char smem[];
    const uint32_t sb = smem_u32(smem);

    const int tid  = threadIdx.x;
    const int lane = tid & 31;
    const int w    = tid >> 5;
    const int wm   = w >> 2;     // 0..3: m-warp (32 rows)
    const int wn   = w & 3;      // 0..3: n-warp (16 cols)
    const int m0   = blockIdx.y * TBM;
    const int d0   = blockIdx.x * TBN;
    const int bn   = blockIdx.x;

    float acc[4][2][2][4] = {};  // [gate][mi][ni][reg]
    float2 hval[2][2][2];        // [ni][mi][p]

    const int NSTAGE = DD / TBK;  // 8
    // stage whose k-range holds this warp's output H columns (uniform per warp)
    const int cstage = 2 * bn + (wn >> 1);

    // ---- staging: global (half) -> smem via cp.async (512 threads) ----
    auto stage = [&](int kc, int buf) {
        const int k0 = kc * TBK;
        {
            int row = tid >> 2;             // 0..127
            int c   = tid & 3;              // 16B chunk (8 halves)
            uint32_t dx = sb + OFF_AX + buf * ABUF + row * ROWB + c * 16;
            CP16(dx, Xh + (size_t)(m0 + row) * DD + k0 + c * 8);
            uint32_t dh = sb + OFF_AH + buf * ABUF + row * ROWB + c * 16;
            CP16(dh, Hh + (size_t)(m0 + row) * DD + k0 + c * 8);
        }
#pragma unroll
        for (int j = 0; j < 3; ++j) {
            int slot = tid + 512 * j;       // 0..1535
            int g = slot >> 8;              // 0..5
            int r = (slot >> 2) & 63;
            int c = slot & 3;
            const __half* W = (g < 3) ? Wih : Whh;
            int grow = (g % 3) * DD + d0 + r;
            uint32_t db = sb + OFF_B + buf * BBUF + g * BGT + r * ROWB + c * 16;
            CP16(db, W + (size_t)grow * DD + k0 + c * 8);
        }
    };

    stage(0, 0); cp_commit();
    stage(1, 1); cp_commit();

    // ldmatrix per-lane address components
    const int rowA  = lane & 15;
    const int colAh = (lane >> 4) * 16;
    const int rowB  = (lane & 7) + ((lane >> 4) * 8);
    const int colBh = ((lane >> 3) & 1) * 16;

#pragma unroll 1
    for (int kc = 0; kc < NSTAGE; ++kc) {
        int buf = kc % NBUF;
        if (kc + 2 < NSTAGE) {
            stage(kc + 2, (kc + 2) % NBUF);
            cp_commit();
            cp_wait<2>();
        } else if (kc + 1 < NSTAGE) {
            cp_wait<1>();
        } else {
            cp_wait<0>();
        }
        __syncthreads();

        if (kc == cstage) {
            // H columns for this warp's outputs live in this AsH tile
            const char* hb = smem + OFF_AH + buf * ABUF;
#pragma unroll
            for (int ni = 0; ni < 2; ++ni)
#pragma unroll
            for (int mi = 0; mi < 2; ++mi)
#pragma unroll
            for (int p = 0; p < 2; ++p) {
                int mr = wm * 32 + mi * 16 + (lane >> 2) + p * 8;
                int cc = (wn & 1) * 16 + ni * 8 + (lane & 3) * 2;
                __half2 hh = *(const __half2*)(hb + mr * ROWB + cc * 2);
                hval[ni][mi][p] = __half22float2(hh);
            }
        }

        const uint32_t aXb = sb + OFF_AX + buf * ABUF;
        const uint32_t aHb = sb + OFF_AH + buf * ABUF;
        const uint32_t bb  = sb + OFF_B  + buf * BBUF;

#pragma unroll
        for (int c = 0; c < 2; ++c) {       // two k16 chunks per stage
            uint32_t aX[2][4], aH[2][4], bf[6][4];
#pragma unroll
            for (int mi = 0; mi < 2; ++mi) {
                uint32_t ra = (wm * 32 + mi * 16 + rowA) * ROWB + c * 32 + colAh;
                ldsm4(aX[mi], aXb + ra);
                ldsm4(aH[mi], aHb + ra);
            }
#pragma unroll
            for (int g = 0; g < 6; ++g) {
                uint32_t rb = g * BGT + (wn * 16 + rowB) * ROWB + c * 32 + colBh;
                ldsm4(bf[g], bb + rb);
            }
#pragma unroll
            for (int mi = 0; mi < 2; ++mi)
#pragma unroll
            for (int ni = 0; ni < 2; ++ni) {
                mma_f16(acc[0][mi][ni], aX[mi], &bf[0][2 * ni]);  // r: X@Wr_ih
                mma_f16(acc[0][mi][ni], aH[mi], &bf[3][2 * ni]);  // r: H@Wr_hh
                mma_f16(acc[1][mi][ni], aX[mi], &bf[1][2 * ni]);  // z: X@Wz_ih
                mma_f16(acc[1][mi][ni], aH[mi], &bf[4][2 * ni]);  // z: H@Wz_hh
                mma_f16(acc[2][mi][ni], aX[mi], &bf[2][2 * ni]);  // i_n
                mma_f16(acc[3][mi][ni], aH[mi], &bf[5][2 * ni]);  // h_n
            }
        }
        __syncthreads();
    }

    // ---- fused GRU epilogue (H blend from registers) ----
    const int mwarp = m0 + wm * 32;
    const int dwarp = d0 + wn * 16;
#pragma unroll
    for (int ni = 0; ni < 2; ++ni) {
        const int dA = dwarp + ni * 8 + (lane & 3) * 2;
        const float brA = __ldg(bih + dA)          + __ldg(bhh + dA);
        const float brB = __ldg(bih + dA + 1)      + __ldg(bhh + dA + 1);
        const float bzA = __ldg(bih + DD + dA)     + __ldg(bhh + DD + dA);
        const float bzB = __ldg(bih + DD + dA + 1) + __ldg(bhh + DD + dA + 1);
        const float biA = __ldg(bih + 2 * DD + dA);
        const float biB = __ldg(bih + 2 * DD + dA + 1);
        const float bnA = __ldg(bhh + 2 * DD + dA);
        const float bnB = __ldg(bhh + 2 * DD + dA + 1);
#pragma unroll
        for (int mi = 0; mi < 2; ++mi) {
#pragma unroll
            for (int p = 0; p < 2; ++p) {
                const int m = mwarp + mi * 16 + (lane >> 2) + p * 8;
                const float cr0 = acc[0][mi][ni][2 * p], cr1 = acc[0][mi][ni][2 * p + 1];
                const float cz0 = acc[1][mi][ni][2 * p], cz1 = acc[1][mi][ni][2 * p + 1];
                const float ci0 = acc[2][mi][ni][2 * p], ci1 = acc[2][mi][ni][2 * p + 1];
                const float cn0 = acc[3][mi][ni][2 * p], cn1 = acc[3][mi][ni][2 * p + 1];
                const float2 h2 = hval[ni][mi][p];
                const float r0 = sigf(cr0 + brA);
                const float r1 = sigf(cr1 + brB);
                const float z0 = sigf(cz0 + bzA);
                const float z1 = sigf(cz1 + bzB);
                const float n0 = tanhf(ci0 + biA + r0 * (cn0 + bnA));
                const float n1 = tanhf(ci1 + biB + r1 * (cn1 + bnB));
                float2 y2;
                y2.x = (1.0f - z0) * n0 + z0 * h2.x;
                y2.y = (1.0f - z1) * n1 + z1 * h2.y;
                *(float2*)(Y + (size_t)m * DD + dA) = y2;
            }
        }
    }
}

// ---------------- driver ----------------
static void run_step(const float* cur_obj, const float* cur_pred,
                     float* next_obj, float* next_pred,
                     const int* pidx,
                     const float* w_e2v, const float* b_e2v,
                     const float* w_v2e, const float* b_v2e,
                     const float* b_ih, const float* b_hh,
                     float* aO1, float* aO2, float* pP1, float* pP2,
                     float* msgO,
                     __half* msgO_h, __half* msgP_h, __half* objH_h, __half* predH_h,
                     const __half* Wih_h, const __half* Whh_h)
{
    // fused: gate scalars + half conversion (single read pass)
    rs_f2h_kernel<<<(N_OBJ * 32 + 255) / 256, 256>>>(cur_obj, N_OBJ, w_e2v, w_v2e + DD,
                                                     aO1, aO2, objH_h);
    rs_f2h_kernel<<<(N_PAIR * 32 + 255) / 256, 256>>>(cur_pred, N_PAIR, w_e2v + DD, w_v2e,
                                                      pP1, pP2, predH_h);
    zero_kernel<<<(N_OBJ * DD / 4 + 255) / 256, 256>>>((float4*)msgO, N_OBJ * DD / 4);
    // gates + scatter: reads half features (already produced above)
    edge_kernel<<<(N_PAIR * 32 + 255) / 256, 256>>>(predH_h, objH_h, pidx,
                                                    aO1, aO2, pP1, pP2,
                                                    b_e2v, b_v2e, msgO, msgP_h);
    f2h_kernel<<<(N_OBJ * DD / 8 + 255) / 256, 256>>>(msgO, msgO_h, N_OBJ * DD / 8);
    gru_fp16<<<dim3(DD / TBN, N_OBJ / TBM), 512, GRU_SMEM>>>(
        msgO_h, objH_h, Wih_h, Whh_h, b_ih, b_hh, next_obj);
    gru_fp16<<<dim3(DD / TBN, N_PAIR / TBM), 512, GRU_SMEM>>>(
        msgP_h, predH_h, Wih_h, Whh_h, b_ih, b_hh, next_pred);
}

extern "C" void kernel_launch(void* const* d_in, const int* in_sizes, int n_in,
                              void* d_out, int out_size)
{
    (void)in_sizes; (void)n_in; (void)out_size;
    const float* x_obj  = (const float*)d_in[0];
    const float* x_pred = (const float*)d_in[1];
    const int*   pidx   = (const int*)d_in[2];
    const float* w_e2v  = (const float*)d_in[3];
    const float* b_e2v  = (const float*)d_in[4];
    const float* w_v2e  = (const float*)d_in[5];
    const float* b_v2e  = (const float*)d_in[6];
    const float* w_ih   = (const float*)d_in[7];
    const float* w_hh   = (const float*)d_in[8];
    const float* b_ih   = (const float*)d_in[9];
    const float* b_hh   = (const float*)d_in[10];
    float* out = (float*)d_out;

    cudaFuncSetAttribute(gru_fp16, cudaFuncAttributeMaxDynamicSharedMemorySize, GRU_SMEM);

    float *objA, *predA, *msgO, *aO1, *aO2, *pP1, *pP2;
    __half *msgP_h, *msgO_h, *objH_h, *predH_h, *Wih_h, *Whh_h;
    cudaGetSymbolAddress((void**)&objA,   g_objA);
    cudaGetSymbolAddress((void**)&predA,  g_predA);
    cudaGetSymbolAddress((void**)&msgO,   g_msgO);
    cudaGetSymbolAddress((void**)&aO1,    g_aO1);
    cudaGetSymbolAddress((void**)&aO2,    g_aO2);
    cudaGetSymbolAddress((void**)&pP1,    g_pP1);
    cudaGetSymbolAddress((void**)&pP2,    g_pP2);
    cudaGetSymbolAddress((void**)&msgP_h, g_msgP_h);
    cudaGetSymbolAddress((void**)&msgO_h, g_msgO_h);
    cudaGetSymbolAddress((void**)&objH_h, g_objH_h);
    cudaGetSymbolAddress((void**)&predH_h,g_predH_h);
    cudaGetSymbolAddress((void**)&Wih_h,  g_Wih_h);
    cudaGetSymbolAddress((void**)&Whh_h,  g_Whh_h);

    // weight conversion (deterministic every call)
    f2h_kernel<<<(3 * DD * DD / 8 + 255) / 256, 256>>>(w_ih, Wih_h, 3 * DD * DD / 8);
    f2h_kernel<<<(3 * DD * DD / 8 + 255) / 256, 256>>>(w_hh, Whh_h, 3 * DD * DD / 8);

    float* out_obj  = out;
    float* out_pred = out + (size_t)N_OBJ * DD;

    run_step(x_obj, x_pred, objA, predA, pidx,
             w_e2v, b_e2v, w_v2e, b_v2e, b_ih, b_hh,
             aO1, aO2, pP1, pP2, msgO,
             msgO_h, msgP_h, objH_h, predH_h, Wih_h, Whh_h);
    run_step(objA, predA, out_obj, out_pred, pidx,
             w_e2v, b_e2v, w_v2e, b_v2e, b_ih, b_hh,
             aO1, aO2, pP1, pP2, msgO,
             msgO_h, msgP_h, objH_h, predH_h, Wih_h, Whh_h);
}

// round 14
// speedup vs baseline: 1.0832x; 1.0832x over previous
#include <cuda_runtime.h>
#include <cuda_fp16.h>
#include <math.h>
#include <stdint.h>

#define N_OBJ  16384
#define N_PAIR 131072
#define DD     256

// ---------------- scratch (static device memory; no allocations) ----------------
__device__ float g_objA[(size_t)N_OBJ  * DD];
__device__ float g_predA[(size_t)N_PAIR * DD];
__device__ float g_msgO[(size_t)N_OBJ  * DD];
__device__ float g_aO1[N_OBJ];
__device__ float g_aO2[N_OBJ];
__device__ float g_pP1[N_PAIR];
__device__ float g_pP2[N_PAIR];
// half-precision MMA operand buffers
__device__ __half g_msgP_h[(size_t)N_PAIR * DD];
__device__ __half g_msgO_h[(size_t)N_OBJ  * DD];
__device__ __half g_objH_h[(size_t)N_OBJ  * DD];
__device__ __half g_predH_h[(size_t)N_PAIR * DD];
__device__ __half g_Wih_h[3 * DD * DD];
__device__ __half g_Whh_h[3 * DD * DD];

__device__ __forceinline__ float sigf(float x) { return 1.0f / (1.0f + expf(-x)); }

// ---------------- float -> half conversion (8 elems / thread) ----------------
__global__ void f2h_kernel(const float* __restrict__ src, __half* __restrict__ dst, int n8)
{
    int i = blockIdx.x * blockDim.x + threadIdx.x;
    if (i >= n8) return;
    const float4* s4 = (const float4*)src;
    float4 a = s4[2 * i];
    float4 b = s4[2 * i + 1];
    __half2 h[4];
    h[0] = __floats2half2_rn(a.x, a.y);
    h[1] = __floats2half2_rn(a.z, a.w);
    h[2] = __floats2half2_rn(b.x, b.y);
    h[3] = __floats2half2_rn(b.z, b.w);
    ((uint4*)dst)[i] = *(uint4*)h;
}

// ---------------- fused per-row gate scalars + half conversion ----------------
__global__ void rs_f2h_kernel(const float* __restrict__ X, int M,
                              const float* __restrict__ wA, const float* __restrict__ wB,
                              float* __restrict__ outA, float* __restrict__ outB,
                              __half* __restrict__ Xh)
{
    int row = (blockIdx.x * blockDim.x + threadIdx.x) >> 5;
    int lane = threadIdx.x & 31;
    if (row >= M) return;
    const float4* xr = (const float4*)(X + (size_t)row * DD);
    const float4* wa4 = (const float4*)wA;
    const float4* wb4 = (const float4*)wB;
    float sA = 0.f, sB = 0.f;
    __half2 hout[4];
#pragma unroll
    for (int h = 0; h < 2; ++h) {
        int c4 = 2 * lane + h;
        float4 v = xr[c4];
        float4 a = wa4[c4];
        float4 b = wb4[c4];
        float rx = fmaxf(v.x, 0.f), ry = fmaxf(v.y, 0.f);
        float rz = fmaxf(v.z, 0.f), rw = fmaxf(v.w, 0.f);
        sA += rx * a.x + ry * a.y + rz * a.z + rw * a.w;
        sB += rx * b.x + ry * b.y + rz * b.z + rw * b.w;
        hout[2 * h]     = __floats2half2_rn(v.x, v.y);
        hout[2 * h + 1] = __floats2half2_rn(v.z, v.w);
    }
    ((uint4*)(Xh + (size_t)row * DD))[lane] = *(uint4*)hout;
#pragma unroll
    for (int o = 16; o > 0; o >>= 1) {
        sA += __shfl_xor_sync(0xFFFFFFFFu, sA, o);
        sB += __shfl_xor_sync(0xFFFFFFFFu, sB, o);
    }
    if (lane == 0) { outA[row] = sA; outB[row] = sB; }
}

// ---------------- zero msgO ----------------
__global__ void zero_kernel(float4* __restrict__ p, int n4)
{
    int i = blockIdx.x * blockDim.x + threadIdx.x;
    if (i < n4) p[i] = make_float4(0.f, 0.f, 0.f, 0.f);
}

// ---------------- edge kernel (fp16 feature reads; msgP half out) ----------------
__global__ void edge_kernel(const __half* __restrict__ xp,   // predH_h
                            const __half* __restrict__ xo,   // objH_h
                            const int*   __restrict__ pidx,
                            const float* __restrict__ aO1, const float* __restrict__ aO2,
                            const float* __restrict__ pP1, const float* __restrict__ pP2,
                            const float* __restrict__ b_e2v, const float* __restrict__ b_v2e,
                            float* __restrict__ msgO, __half* __restrict__ msgP)
{
    int e = (blockIdx.x * blockDim.x + threadIdx.x) >> 5;
    int lane = threadIdx.x & 31;
    if (e >= N_PAIR) return;

    int s = pidx[2 * e];
    int o = pidx[2 * e + 1];
    float be = b_e2v[0];
    float bv = b_v2e[0];
    float p1 = pP1[e], p2 = pP2[e];
    float g1 = sigf(aO1[s] + p1 + be);   // m_subj = g1 * x_pred[e] -> msgO[s]
    float g2 = sigf(aO1[o] + p1 + be);   // m_obj  = g2 * x_pred[e] -> msgO[o]
    float gs = sigf(aO2[s] + p2 + bv);   // m_s2p  = gs * x_obj[s]
    float go = sigf(aO2[o] + p2 + bv);   // m_o2p  = go * x_obj[o]

    // each lane handles 8 halves = one uint4 per row
    uint4 vp = ((const uint4*)(xp + (size_t)e * DD))[lane];
    uint4 vs = ((const uint4*)(xo + (size_t)s * DD))[lane];
    uint4 vo = ((const uint4*)(xo + (size_t)o * DD))[lane];
    const __half2* vph = (const __half2*)&vp;
    const __half2* vsh = (const __half2*)&vs;
    const __half2* voh = (const __half2*)&vo;

    __half2 mpout[4];
    float a1[8], a2[8];
#pragma unroll
    for (int q = 0; q < 4; ++q) {
        float2 p  = __half22float2(vph[q]);
        float2 sv = __half22float2(vsh[q]);
        float2 ov = __half22float2(voh[q]);
        mpout[q] = __floats2half2_rn(gs * sv.x + go * ov.x, gs * sv.y + go * ov.y);
        a1[2 * q] = g1 * p.x; a1[2 * q + 1] = g1 * p.y;
        a2[2 * q] = g2 * p.x; a2[2 * q + 1] = g2 * p.y;
    }
    ((uint4*)(msgP + (size_t)e * DD))[lane] = *(uint4*)mpout;

    float4* mos = (float4*)(msgO + (size_t)s * DD);
    float4* moo = (float4*)(msgO + (size_t)o * DD);
    atomicAdd(&mos[2 * lane],     make_float4(a1[0], a1[1], a1[2], a1[3]));
    atomicAdd(&mos[2 * lane + 1], make_float4(a1[4], a1[5], a1[6], a1[7]));
    atomicAdd(&moo[2 * lane],     make_float4(a2[0], a2[1], a2[2], a2[3]));
    atomicAdd(&moo[2 * lane + 1], make_float4(a2[4], a2[5], a2[6], a2[7]));
}

// ================= fp16 mma.sync fused GRU (R12 config) =================
// Y = GRU(X, H). 4 accumulator groups:
//   accR = X@Wr_ih^T + H@Wr_hh^T ; accZ likewise ; accI = X@Wn_ih^T ; accN = H@Wn_hh^T
// BM=128, BN=32, BK=32 halves; 256 threads (8 warps: 4m x 2n, warp tile 32x16).
// 3-stage cp.async ring, 2 CTAs/SM. H blend captured from AsH staging tile at
// stage kc == blockIdx.x (K-range == D-range): no gmem H read in the epilogue.
#define TBM 128
#define TBN 32
#define TBK 32            // halves per stage
#define ROWB 80           // smem row stride bytes (40 halves)
#define NBUF 3

#define ABUF (TBM * ROWB)            // 10240 B per matrix per buffer
#define BGT  (TBN * ROWB)            // 2560 B per gate tile
#define BBUF (6 * BGT)               // 15360 B per buffer
#define OFF_AX 0
#define OFF_AH (NBUF * ABUF)         // 30720
#define OFF_B  (2 * NBUF * ABUF)     // 61440
#define GRU_SMEM (OFF_B + NBUF * BBUF)  // 107520

__device__ __forceinline__ uint32_t smem_u32(const void* p) {
    return (uint32_t)__cvta_generic_to_shared(p);
}
#define CP16(dst, src) \
    asm volatile("cp.async.cg.shared.global [%0], [%1], 16;\n" :: "r"(dst), "l"(src) : "memory")
__device__ __forceinline__ void cp_commit() {
    asm volatile("cp.async.commit_group;\n" ::: "memory");
}
template<int N> __device__ __forceinline__ void cp_wait() {
    asm volatile("cp.async.wait_group %0;\n" :: "n"(N) : "memory");
}
__device__ __forceinline__ void ldsm4(uint32_t* r, uint32_t addr) {
    asm volatile("ldmatrix.sync.aligned.m8n8.x4.shared.b16 {%0,%1,%2,%3}, [%4];\n"
        : "=r"(r[0]), "=r"(r[1]), "=r"(r[2]), "=r"(r[3]) : "r"(addr));
}
__device__ __forceinline__ void mma_f16(float* c, const uint32_t* a, const uint32_t* b) {
    asm volatile("mma.sync.aligned.m16n8k16.row.col.f32.f16.f16.f32 "
        "{%0,%1,%2,%3}, {%4,%5,%6,%7}, {%8,%9}, {%0,%1,%2,%3};\n"
        : "+f"(c[0]), "+f"(c[1]), "+f"(c[2]), "+f"(c[3])
        : "r"(a[0]), "r"(a[1]), "r"(a[2]), "r"(a[3]), "r"(b[0]), "r"(b[1]));
}

__global__ __launch_bounds__(256, 2)
void gru_fp16(const __half* __restrict__ Xh, const __half* __restrict__ Hh,
              const __half* __restrict__ Wih, const __half* __restrict__ Whh,
              const float* __restrict__ bih, const float* __restrict__ bhh,
              float* __restrict__ Y)
{
    extern __shared__ __align__(128) char smem[];
    const uint32_t sb = smem_u32(smem);

    const int tid  = threadIdx.x;
    const int lane = tid & 31;
    const int w    = tid >> 5;
    const int wm   = w >> 1;     // 0..3
    const int wn   = w & 1;      // 0..1
    const int m0   = blockIdx.y * TBM;
    const int d0   = blockIdx.x * TBN;
    const int bn   = blockIdx.x;  // d-block == k-stage index holding our H cols

    float acc[4][2][2][4] = {};  // [gate][mi][ni][reg]
    float2 hval[2][2][2];        // [ni][mi][p]

    const int NSTAGE = DD / TBK;  // 8

    // ---- staging: global (half) -> smem via cp.async ----
    auto stage = [&](int kc, int buf) {
        const int k0 = kc * TBK;
#pragma unroll
        for (int j = 0; j < 2; ++j) {
            int slot = tid + 256 * j;       // 0..511
            int row = slot >> 2;            // 0..127
            int c   = slot & 3;             // 16B chunk (8 halves)
            uint32_t dx = sb + OFF_AX + buf * ABUF + row * ROWB + c * 16;
            CP16(dx, Xh + (size_t)(m0 + row) * DD + k0 + c * 8);
            uint32_t dh = sb + OFF_AH + buf * ABUF + row * ROWB + c * 16;
            CP16(dh, Hh + (size_t)(m0 + row) * DD + k0 + c * 8);
        }
#pragma unroll
        for (int j = 0; j < 3; ++j) {
            int slot = tid + 256 * j;       // 0..767
            int g = slot >> 7;              // 0..5
            int r = (slot >> 2) & 31;
            int c = slot & 3;
            const __half* W = (g < 3) ? Wih : Whh;
            int grow = (g % 3) * DD + d0 + r;
            uint32_t db = sb + OFF_B + buf * BBUF + g * BGT + r * ROWB + c * 16;
            CP16(db, W + (size_t)grow * DD + k0 + c * 8);
        }
    };

    stage(0, 0); cp_commit();
    stage(1, 1); cp_commit();

    // ldmatrix per-lane address components
    const int rowA  = lane & 15;
    const int colAh = (lane >> 4) * 16;
    const int rowB  = (lane & 7) + ((lane >> 4) * 8);
    const int colBh = ((lane >> 3) & 1) * 16;

#pragma unroll 1
    for (int kc = 0; kc < NSTAGE; ++kc) {
        int buf = kc % NBUF;
        if (kc + 2 < NSTAGE) {
            stage(kc + 2, (kc + 2) % NBUF);
            cp_commit();
            cp_wait<2>();
        } else if (kc + 1 < NSTAGE) {
            cp_wait<1>();
        } else {
            cp_wait<0>();
        }
        __syncthreads();

        if (kc == bn) {
            // H columns for this block's outputs live in this AsH tile
            const char* hb = smem + OFF_AH + buf * ABUF;
#pragma unroll
            for (int ni = 0; ni < 2; ++ni)
#pragma unroll
            for (int mi = 0; mi < 2; ++mi)
#pragma unroll
            for (int p = 0; p < 2; ++p) {
                int mr = wm * 32 + mi * 16 + (lane >> 2) + p * 8;
                int cc = wn * 16 + ni * 8 + (lane & 3) * 2;
                __half2 hh = *(const __half2*)(hb + mr * ROWB + cc * 2);
                hval[ni][mi][p] = __half22float2(hh);
            }
        }

        const uint32_t aXb = sb + OFF_AX + buf * ABUF;
        const uint32_t aHb = sb + OFF_AH + buf * ABUF;
        const uint32_t bb  = sb + OFF_B  + buf * BBUF;

#pragma unroll
        for (int c = 0; c < 2; ++c) {       // two k16 chunks per stage
            uint32_t aX[2][4], aH[2][4], bf[6][4];
#pragma unroll
            for (int mi = 0; mi < 2; ++mi) {
                uint32_t ra = (wm * 32 + mi * 16 + rowA) * ROWB + c * 32 + colAh;
                ldsm4(aX[mi], aXb + ra);
                ldsm4(aH[mi], aHb + ra);
            }
#pragma unroll
            for (int g = 0; g < 6; ++g) {
                uint32_t rb = g * BGT + (wn * 16 + rowB) * ROWB + c * 32 + colBh;
                ldsm4(bf[g], bb + rb);
            }
#pragma unroll
            for (int mi = 0; mi < 2; ++mi)
#pragma unroll
            for (int ni = 0; ni < 2; ++ni) {
                mma_f16(acc[0][mi][ni], aX[mi], &bf[0][2 * ni]);  // r: X@Wr_ih
                mma_f16(acc[0][mi][ni], aH[mi], &bf[3][2 * ni]);  // r: H@Wr_hh
                mma_f16(acc[1][mi][ni], aX[mi], &bf[1][2 * ni]);  // z: X@Wz_ih
                mma_f16(acc[1][mi][ni], aH[mi], &bf[4][2 * ni]);  // z: H@Wz_hh
                mma_f16(acc[2][mi][ni], aX[mi], &bf[2][2 * ni]);  // i_n
                mma_f16(acc[3][mi][ni], aH[mi], &bf[5][2 * ni]);  // h_n
            }
        }
        __syncthreads();
    }

    // ---- fused GRU epilogue (H blend from registers) ----
    const int mwarp = m0 + wm * 32;
    const int dwarp = d0 + wn * 16;
#pragma unroll
    for (int ni = 0; ni < 2; ++ni) {
        const int dA = dwarp + ni * 8 + (lane & 3) * 2;
        const float brA = __ldg(bih + dA)          + __ldg(bhh + dA);
        const float brB = __ldg(bih + dA + 1)      + __ldg(bhh + dA + 1);
        const float bzA = __ldg(bih + DD + dA)     + __ldg(bhh + DD + dA);
        const float bzB = __ldg(bih + DD + dA + 1) + __ldg(bhh + DD + dA + 1);
        const float biA = __ldg(bih + 2 * DD + dA);
        const float biB = __ldg(bih + 2 * DD + dA + 1);
        const float bnA = __ldg(bhh + 2 * DD + dA);
        const float bnB = __ldg(bhh + 2 * DD + dA + 1);
#pragma unroll
        for (int mi = 0; mi < 2; ++mi) {
#pragma unroll
            for (int p = 0; p < 2; ++p) {
                const int m = mwarp + mi * 16 + (lane >> 2) + p * 8;
                const float cr0 = acc[0][mi][ni][2 * p], cr1 = acc[0][mi][ni][2 * p + 1];
                const float cz0 = acc[1][mi][ni][2 * p], cz1 = acc[1][mi][ni][2 * p + 1];
                const float ci0 = acc[2][mi][ni][2 * p], ci1 = acc[2][mi][ni][2 * p + 1];
                const float cn0 = acc[3][mi][ni][2 * p], cn1 = acc[3][mi][ni][2 * p + 1];
                const float2 h2 = hval[ni][mi][p];
                const float r0 = sigf(cr0 + brA);
                const float r1 = sigf(cr1 + brB);
                const float z0 = sigf(cz0 + bzA);
                const float z1 = sigf(cz1 + bzB);
                const float n0 = tanhf(ci0 + biA + r0 * (cn0 + bnA));
                const float n1 = tanhf(ci1 + biB + r1 * (cn1 + bnB));
                float2 y2;
                y2.x = (1.0f - z0) * n0 + z0 * h2.x;
                y2.y = (1.0f - z1) * n1 + z1 * h2.y;
                *(float2*)(Y + (size_t)m * DD + dA) = y2;
            }
        }
    }
}

// ---------------- driver ----------------
static void run_step(const float* cur_obj, const float* cur_pred,
                     float* next_obj, float* next_pred,
                     const int* pidx,
                     const float* w_e2v, const float* b_e2v,
                     const float* w_v2e, const float* b_v2e,
                     const float* b_ih, const float* b_hh,
                     float* aO1, float* aO2, float* pP1, float* pP2,
                     float* msgO,
                     __half* msgO_h, __half* msgP_h, __half* objH_h, __half* predH_h,
                     const __half* Wih_h, const __half* Whh_h)
{
    // fused: gate scalars + half conversion (single read pass)
    rs_f2h_kernel<<<(N_OBJ * 32 + 255) / 256, 256>>>(cur_obj, N_OBJ, w_e2v, w_v2e + DD,
                                                     aO1, aO2, objH_h);
    rs_f2h_kernel<<<(N_PAIR * 32 + 255) / 256, 256>>>(cur_pred, N_PAIR, w_e2v + DD, w_v2e,
                                                      pP1, pP2, predH_h);
    zero_kernel<<<(N_OBJ * DD / 4 + 255) / 256, 256>>>((float4*)msgO, N_OBJ * DD / 4);
    // gates + scatter: reads half features (already produced above)
    edge_kernel<<<(N_PAIR * 32 + 255) / 256, 256>>>(predH_h, objH_h, pidx,
                                                    aO1, aO2, pP1, pP2,
                                                    b_e2v, b_v2e, msgO, msgP_h);
    f2h_kernel<<<(N_OBJ * DD / 8 + 255) / 256, 256>>>(msgO, msgO_h, N_OBJ * DD / 8);
    gru_fp16<<<dim3(DD / TBN, N_OBJ / TBM), 256, GRU_SMEM>>>(
        msgO_h, objH_h, Wih_h, Whh_h, b_ih, b_hh, next_obj);
    gru_fp16<<<dim3(DD / TBN, N_PAIR / TBM), 256, GRU_SMEM>>>(
        msgP_h, predH_h, Wih_h, Whh_h, b_ih, b_hh, next_pred);
}

extern "C" void kernel_launch(void* const* d_in, const int* in_sizes, int n_in,
                              void* d_out, int out_size)
{
    (void)in_sizes; (void)n_in; (void)out_size;
    const float* x_obj  = (const float*)d_in[0];
    const float* x_pred = (const float*)d_in[1];
    const int*   pidx   = (const int*)d_in[2];
    const float* w_e2v  = (const float*)d_in[3];
    const float* b_e2v  = (const float*)d_in[4];
    const float* w_v2e  = (const float*)d_in[5];
    const float* b_v2e  = (const float*)d_in[6];
    const float* w_ih   = (const float*)d_in[7];
    const float* w_hh   = (const float*)d_in[8];
    const float* b_ih   = (const float*)d_in[9];
    const float* b_hh   = (const float*)d_in[10];
    float* out = (float*)d_out;

    cudaFuncSetAttribute(gru_fp16, cudaFuncAttributeMaxDynamicSharedMemorySize, GRU_SMEM);

    float *objA, *predA, *msgO, *aO1, *aO2, *pP1, *pP2;
    __half *msgP_h, *msgO_h, *objH_h, *predH_h, *Wih_h, *Whh_h;
    cudaGetSymbolAddress((void**)&objA,   g_objA);
    cudaGetSymbolAddress((void**)&predA,  g_predA);
    cudaGetSymbolAddress((void**)&msgO,   g_msgO);
    cudaGetSymbolAddress((void**)&aO1,    g_aO1);
    cudaGetSymbolAddress((void**)&aO2,    g_aO2);
    cudaGetSymbolAddress((void**)&pP1,    g_pP1);
    cudaGetSymbolAddress((void**)&pP2,    g_pP2);
    cudaGetSymbolAddress((void**)&msgP_h, g_msgP_h);
    cudaGetSymbolAddress((void**)&msgO_h, g_msgO_h);
    cudaGetSymbolAddress((void**)&objH_h, g_objH_h);
    cudaGetSymbolAddress((void**)&predH_h,g_predH_h);
    cudaGetSymbolAddress((void**)&Wih_h,  g_Wih_h);
    cudaGetSymbolAddress((void**)&Whh_h,  g_Whh_h);

    // weight conversion (deterministic every call)
    f2h_kernel<<<(3 * DD * DD / 8 + 255) / 256, 256>>>(w_ih, Wih_h, 3 * DD * DD / 8);
    f2h_kernel<<<(3 * DD * DD / 8 + 255) / 256, 256>>>(w_hh, Whh_h, 3 * DD * DD / 8);

    float* out_obj  = out;
    float* out_pred = out + (size_t)N_OBJ * DD;

    run_step(x_obj, x_pred, objA, predA, pidx,
             w_e2v, b_e2v, w_v2e, b_v2e, b_ih, b_hh,
             aO1, aO2, pP1, pP2, msgO,
             msgO_h, msgP_h, objH_h, predH_h, Wih_h, Whh_h);
    run_step(objA, predA, out_obj, out_pred, pidx,
             w_e2v, b_e2v, w_v2e, b_v2e, b_ih, b_hh,
             aO1, aO2, pP1, pP2, msgO,
             msgO_h, msgP_h, objH_h, predH_h, Wih_h, Whh_h);
}

// round 15
// speedup vs baseline: 1.1100x; 1.0248x over previous
#include <cuda_runtime.h>
#include <cuda_fp16.h>
#include <math.h>
#include <stdint.h>

#define N_OBJ  16384
#define N_PAIR 131072
#define DD     256

// ---------------- scratch (static device memory; no allocations) ----------------
__device__ float g_objA[(size_t)N_OBJ  * DD];   // float intermediates after step 0
__device__ float g_predA[(size_t)N_PAIR * DD];
__device__ float g_msgO[(size_t)N_OBJ  * DD];
__device__ float g_aO1[N_OBJ];
__device__ float g_aO2[N_OBJ];
__device__ float g_pP1[N_PAIR];
__device__ float g_pP2[N_PAIR];
// half-precision MMA operand buffers
__device__ __half g_msgP_h[(size_t)N_PAIR * DD];
__device__ __half g_msgO_h[(size_t)N_OBJ  * DD];
__device__ __half g_objH_h[(size_t)N_OBJ  * DD];   // half(x_obj)  (step-0 H operand)
__device__ __half g_predH_h[(size_t)N_PAIR * DD];  // half(x_pred)
__device__ __half g_objB_h[(size_t)N_OBJ  * DD];   // half(objA)   (step-1 H operand)
__device__ __half g_predB_h[(size_t)N_PAIR * DD];  // half(predA)
__device__ __half g_Wih_h[3 * DD * DD];
__device__ __half g_Whh_h[3 * DD * DD];

__device__ __forceinline__ float sigf(float x) { return 1.0f / (1.0f + expf(-x)); }

// ---------------- float -> half conversion (8 elems / thread) ----------------
__global__ void f2h_kernel(const float* __restrict__ src, __half* __restrict__ dst, int n8)
{
    int i = blockIdx.x * blockDim.x + threadIdx.x;
    if (i >= n8) return;
    const float4* s4 = (const float4*)src;
    float4 a = s4[2 * i];
    float4 b = s4[2 * i + 1];
    __half2 h[4];
    h[0] = __floats2half2_rn(a.x, a.y);
    h[1] = __floats2half2_rn(a.z, a.w);
    h[2] = __floats2half2_rn(b.x, b.y);
    h[3] = __floats2half2_rn(b.z, b.w);
    ((uint4*)dst)[i] = *(uint4*)h;
}

// ---------------- fused per-row gate scalars + half conversion (float input) ----
__global__ void rs_f2h_kernel(const float* __restrict__ X, int M,
                              const float* __restrict__ wA, const float* __restrict__ wB,
                              float* __restrict__ outA, float* __restrict__ outB,
                              __half* __restrict__ Xh)
{
    int row = (blockIdx.x * blockDim.x + threadIdx.x) >> 5;
    int lane = threadIdx.x & 31;
    if (row >= M) return;
    const float4* xr = (const float4*)(X + (size_t)row * DD);
    const float4* wa4 = (const float4*)wA;
    const float4* wb4 = (const float4*)wB;
    float sA = 0.f, sB = 0.f;
    __half2 hout[4];
#pragma unroll
    for (int h = 0; h < 2; ++h) {
        int c4 = 2 * lane + h;
        float4 v = xr[c4];
        float4 a = wa4[c4];
        float4 b = wb4[c4];
        float rx = fmaxf(v.x, 0.f), ry = fmaxf(v.y, 0.f);
        float rz = fmaxf(v.z, 0.f), rw = fmaxf(v.w, 0.f);
        sA += rx * a.x + ry * a.y + rz * a.z + rw * a.w;
        sB += rx * b.x + ry * b.y + rz * b.z + rw * b.w;
        hout[2 * h]     = __floats2half2_rn(v.x, v.y);
        hout[2 * h + 1] = __floats2half2_rn(v.z, v.w);
    }
    ((uint4*)(Xh + (size_t)row * DD))[lane] = *(uint4*)hout;
#pragma unroll
    for (int o = 16; o > 0; o >>= 1) {
        sA += __shfl_xor_sync(0xFFFFFFFFu, sA, o);
        sB += __shfl_xor_sync(0xFFFFFFFFu, sB, o);
    }
    if (lane == 0) { outA[row] = sA; outB[row] = sB; }
}

// ---------------- per-row gate scalars from HALF features (no writes) ----------
__global__ void rs_half_kernel(const __half* __restrict__ X, int M,
                               const float* __restrict__ wA, const float* __restrict__ wB,
                               float* __restrict__ outA, float* __restrict__ outB)
{
    int row = (blockIdx.x * blockDim.x + threadIdx.x) >> 5;
    int lane = threadIdx.x & 31;
    if (row >= M) return;
    uint4 v = ((const uint4*)(X + (size_t)row * DD))[lane];   // 8 halves
    const __half2* vh = (const __half2*)&v;
    const float4* wa4 = (const float4*)wA;
    const float4* wb4 = (const float4*)wB;
    float4 a0 = wa4[2 * lane], a1 = wa4[2 * lane + 1];
    float4 b0 = wb4[2 * lane], b1 = wb4[2 * lane + 1];
    float aw[8] = {a0.x, a0.y, a0.z, a0.w, a1.x, a1.y, a1.z, a1.w};
    float bw[8] = {b0.x, b0.y, b0.z, b0.w, b1.x, b1.y, b1.z, b1.w};
    float sA = 0.f, sB = 0.f;
#pragma unroll
    for (int q = 0; q < 4; ++q) {
        float2 f = __half22float2(vh[q]);
        float r0 = fmaxf(f.x, 0.f), r1 = fmaxf(f.y, 0.f);
        sA += r0 * aw[2 * q] + r1 * aw[2 * q + 1];
        sB += r0 * bw[2 * q] + r1 * bw[2 * q + 1];
    }
#pragma unroll
    for (int o = 16; o > 0; o >>= 1) {
        sA += __shfl_xor_sync(0xFFFFFFFFu, sA, o);
        sB += __shfl_xor_sync(0xFFFFFFFFu, sB, o);
    }
    if (lane == 0) { outA[row] = sA; outB[row] = sB; }
}

// ---------------- zero msgO ----------------
__global__ void zero_kernel(float4* __restrict__ p, int n4)
{
    int i = blockIdx.x * blockDim.x + threadIdx.x;
    if (i < n4) p[i] = make_float4(0.f, 0.f, 0.f, 0.f);
}

// ---------------- edge kernel (R12 float version; msgP half out) ----------------
__global__ void edge_kernel(const float* __restrict__ xp,
                            const float* __restrict__ xo,
                            const int*   __restrict__ pidx,
                            const float* __restrict__ aO1, const float* __restrict__ aO2,
                            const float* __restrict__ pP1, const float* __restrict__ pP2,
                            const float* __restrict__ b_e2v, const float* __restrict__ b_v2e,
                            float* __restrict__ msgO, __half* __restrict__ msgP)
{
    int e = (blockIdx.x * blockDim.x + threadIdx.x) >> 5;
    int lane = threadIdx.x & 31;
    if (e >= N_PAIR) return;

    int s = pidx[2 * e];
    int o = pidx[2 * e + 1];
    float be = b_e2v[0];
    float bv = b_v2e[0];
    float p1 = pP1[e], p2 = pP2[e];
    float g1 = sigf(aO1[s] + p1 + be);
    float g2 = sigf(aO1[o] + p1 + be);
    float gs = sigf(aO2[s] + p2 + bv);
    float go = sigf(aO2[o] + p2 + bv);

    const float4* xpr = (const float4*)(xp + (size_t)e * DD);
    const float4* xsr = (const float4*)(xo + (size_t)s * DD);
    const float4* xor4 = (const float4*)(xo + (size_t)o * DD);
    __half2* mp = (__half2*)(msgP + (size_t)e * DD);
    float4* mos = (float4*)(msgO + (size_t)s * DD);
    float4* moo = (float4*)(msgO + (size_t)o * DD);

#pragma unroll
    for (int h = 0; h < 2; ++h) {
        int c = lane + h * 32;
        float4 vp = xpr[c];
        float4 vs = xsr[c];
        float4 vo = xor4[c];

        float ox = gs * vs.x + go * vo.x;
        float oy = gs * vs.y + go * vo.y;
        float oz = gs * vs.z + go * vo.z;
        float ow = gs * vs.w + go * vo.w;
        mp[2 * c]     = __floats2half2_rn(ox, oy);
        mp[2 * c + 1] = __floats2half2_rn(oz, ow);

        float4 as = make_float4(g1 * vp.x, g1 * vp.y, g1 * vp.z, g1 * vp.w);
        float4 ao = make_float4(g2 * vp.x, g2 * vp.y, g2 * vp.z, g2 * vp.w);
        atomicAdd(&mos[c], as);
        atomicAdd(&moo[c], ao);
    }
}

// ================= fp16 mma.sync fused GRU (R12 config + optional half Y) ======
#define TBM 128
#define TBN 32
#define TBK 32            // halves per stage
#define ROWB 80           // smem row stride bytes (40 halves)
#define NBUF 3

#define ABUF (TBM * ROWB)            // 10240 B per matrix per buffer
#define BGT  (TBN * ROWB)            // 2560 B per gate tile
#define BBUF (6 * BGT)               // 15360 B per buffer
#define OFF_AX 0
#define OFF_AH (NBUF * ABUF)         // 30720
#define OFF_B  (2 * NBUF * ABUF)     // 61440
#define GRU_SMEM (OFF_B + NBUF * BBUF)  // 107520

__device__ __forceinline__ uint32_t smem_u32(const void* p) {
    return (uint32_t)__cvta_generic_to_shared(p);
}
#define CP16(dst, src) \
    asm volatile("cp.async.cg.shared.global [%0], [%1], 16;\n" :: "r"(dst), "l"(src) : "memory")
__device__ __forceinline__ void cp_commit() {
    asm volatile("cp.async.commit_group;\n" ::: "memory");
}
template<int N> __device__ __forceinline__ void cp_wait() {
    asm volatile("cp.async.wait_group %0;\n" :: "n"(N) : "memory");
}
__device__ __forceinline__ void ldsm4(uint32_t* r, uint32_t addr) {
    asm volatile("ldmatrix.sync.aligned.m8n8.x4.shared.b16 {%0,%1,%2,%3}, [%4];\n"
        : "=r"(r[0]), "=r"(r[1]), "=r"(r[2]), "=r"(r[3]) : "r"(addr));
}
__device__ __forceinline__ void mma_f16(float* c, const uint32_t* a, const uint32_t* b) {
    asm volatile("mma.sync.aligned.m16n8k16.row.col.f32.f16.f16.f32 "
        "{%0,%1,%2,%3}, {%4,%5,%6,%7}, {%8,%9}, {%0,%1,%2,%3};\n"
        : "+f"(c[0]), "+f"(c[1]), "+f"(c[2]), "+f"(c[3])
        : "r"(a[0]), "r"(a[1]), "r"(a[2]), "r"(a[3]), "r"(b[0]), "r"(b[1]));
}

__global__ __launch_bounds__(256, 2)
void gru_fp16(const __half* __restrict__ Xh, const __half* __restrict__ Hh,
              const __half* __restrict__ Wih, const __half* __restrict__ Whh,
              const float* __restrict__ bih, const float* __restrict__ bhh,
              float* __restrict__ Y, __half* __restrict__ Yh)
{
    extern __shared__ __align__(128) char smem[];
    const uint32_t sb = smem_u32(smem);

    const int tid  = threadIdx.x;
    const int lane = tid & 31;
    const int w    = tid >> 5;
    const int wm   = w >> 1;     // 0..3
    const int wn   = w & 1;      // 0..1
    const int m0   = blockIdx.y * TBM;
    const int d0   = blockIdx.x * TBN;
    const int bn   = blockIdx.x;  // d-block == k-stage index holding our H cols

    float acc[4][2][2][4] = {};  // [gate][mi][ni][reg]
    float2 hval[2][2][2];        // [ni][mi][p]

    const int NSTAGE = DD / TBK;  // 8

    auto stage = [&](int kc, int buf) {
        const int k0 = kc * TBK;
#pragma unroll
        for (int j = 0; j < 2; ++j) {
            int slot = tid + 256 * j;       // 0..511
            int row = slot >> 2;            // 0..127
            int c   = slot & 3;             // 16B chunk (8 halves)
            uint32_t dx = sb + OFF_AX + buf * ABUF + row * ROWB + c * 16;
            CP16(dx, Xh + (size_t)(m0 + row) * DD + k0 + c * 8);
            uint32_t dh = sb + OFF_AH + buf * ABUF + row * ROWB + c * 16;
            CP16(dh, Hh + (size_t)(m0 + row) * DD + k0 + c * 8);
        }
#pragma unroll
        for (int j = 0; j < 3; ++j) {
            int slot = tid + 256 * j;       // 0..767
            int g = slot >> 7;              // 0..5
            int r = (slot >> 2) & 31;
            int c = slot & 3;
            const __half* W = (g < 3) ? Wih : Whh;
            int grow = (g % 3) * DD + d0 + r;
            uint32_t db = sb + OFF_B + buf * BBUF + g * BGT + r * ROWB + c * 16;
            CP16(db, W + (size_t)grow * DD + k0 + c * 8);
        }
    };

    stage(0, 0); cp_commit();
    stage(1, 1); cp_commit();

    const int rowA  = lane & 15;
    const int colAh = (lane >> 4) * 16;
    const int rowB  = (lane & 7) + ((lane >> 4) * 8);
    const int colBh = ((lane >> 3) & 1) * 16;

#pragma unroll 1
    for (int kc = 0; kc < NSTAGE; ++kc) {
        int buf = kc % NBUF;
        if (kc + 2 < NSTAGE) {
            stage(kc + 2, (kc + 2) % NBUF);
            cp_commit();
            cp_wait<2>();
        } else if (kc + 1 < NSTAGE) {
            cp_wait<1>();
        } else {
            cp_wait<0>();
        }
        __syncthreads();

        if (kc == bn) {
            const char* hb = smem + OFF_AH + buf * ABUF;
#pragma unroll
            for (int ni = 0; ni < 2; ++ni)
#pragma unroll
            for (int mi = 0; mi < 2; ++mi)
#pragma unroll
            for (int p = 0; p < 2; ++p) {
                int mr = wm * 32 + mi * 16 + (lane >> 2) + p * 8;
                int cc = wn * 16 + ni * 8 + (lane & 3) * 2;
                __half2 hh = *(const __half2*)(hb + mr * ROWB + cc * 2);
                hval[ni][mi][p] = __half22float2(hh);
            }
        }

        const uint32_t aXb = sb + OFF_AX + buf * ABUF;
        const uint32_t aHb = sb + OFF_AH + buf * ABUF;
        const uint32_t bb  = sb + OFF_B  + buf * BBUF;

#pragma unroll
        for (int c = 0; c < 2; ++c) {
            uint32_t aX[2][4], aH[2][4], bf[6][4];
#pragma unroll
            for (int mi = 0; mi < 2; ++mi) {
                uint32_t ra = (wm * 32 + mi * 16 + rowA) * ROWB + c * 32 + colAh;
                ldsm4(aX[mi], aXb + ra);
                ldsm4(aH[mi], aHb + ra);
            }
#pragma unroll
            for (int g = 0; g < 6; ++g) {
                uint32_t rb = g * BGT + (wn * 16 + rowB) * ROWB + c * 32 + colBh;
                ldsm4(bf[g], bb + rb);
            }
#pragma unroll
            for (int mi = 0; mi < 2; ++mi)
#pragma unroll
            for (int ni = 0; ni < 2; ++ni) {
                mma_f16(acc[0][mi][ni], aX[mi], &bf[0][2 * ni]);  // r: X@Wr_ih
                mma_f16(acc[0][mi][ni], aH[mi], &bf[3][2 * ni]);  // r: H@Wr_hh
                mma_f16(acc[1][mi][ni], aX[mi], &bf[1][2 * ni]);  // z: X@Wz_ih
                mma_f16(acc[1][mi][ni], aH[mi], &bf[4][2 * ni]);  // z: H@Wz_hh
                mma_f16(acc[2][mi][ni], aX[mi], &bf[2][2 * ni]);  // i_n
                mma_f16(acc[3][mi][ni], aH[mi], &bf[5][2 * ni]);  // h_n
            }
        }
        __syncthreads();
    }

    // ---- fused GRU epilogue (H blend from registers; optional half output) ----
    const int mwarp = m0 + wm * 32;
    const int dwarp = d0 + wn * 16;
#pragma unroll
    for (int ni = 0; ni < 2; ++ni) {
        const int dA = dwarp + ni * 8 + (lane & 3) * 2;
        const float brA = __ldg(bih + dA)          + __ldg(bhh + dA);
        const float brB = __ldg(bih + dA + 1)      + __ldg(bhh + dA + 1);
        const float bzA = __ldg(bih + DD + dA)     + __ldg(bhh + DD + dA);
        const float bzB = __ldg(bih + DD + dA + 1) + __ldg(bhh + DD + dA + 1);
        const float biA = __ldg(bih + 2 * DD + dA);
        const float biB = __ldg(bih + 2 * DD + dA + 1);
        const float bnA = __ldg(bhh + 2 * DD + dA);
        const float bnB = __ldg(bhh + 2 * DD + dA + 1);
#pragma unroll
        for (int mi = 0; mi < 2; ++mi) {
#pragma unroll
            for (int p = 0; p < 2; ++p) {
                const int m = mwarp + mi * 16 + (lane >> 2) + p * 8;
                const float cr0 = acc[0][mi][ni][2 * p], cr1 = acc[0][mi][ni][2 * p + 1];
                const float cz0 = acc[1][mi][ni][2 * p], cz1 = acc[1][mi][ni][2 * p + 1];
                const float ci0 = acc[2][mi][ni][2 * p], ci1 = acc[2][mi][ni][2 * p + 1];
                const float cn0 = acc[3][mi][ni][2 * p], cn1 = acc[3][mi][ni][2 * p + 1];
                const float2 h2 = hval[ni][mi][p];
                const float r0 = sigf(cr0 + brA);
                const float r1 = sigf(cr1 + brB);
                const float z0 = sigf(cz0 + bzA);
                const float z1 = sigf(cz1 + bzB);
                const float n0 = tanhf(ci0 + biA + r0 * (cn0 + bnA));
                const float n1 = tanhf(ci1 + biB + r1 * (cn1 + bnB));
                float2 y2;
                y2.x = (1.0f - z0) * n0 + z0 * h2.x;
                y2.y = (1.0f - z1) * n1 + z1 * h2.y;
                *(float2*)(Y + (size_t)m * DD + dA) = y2;
                if (Yh) {
                    *(__half2*)(Yh + (size_t)m * DD + dA) = __floats2half2_rn(y2.x, y2.y);
                }
            }
        }
    }
}

// ---------------- driver ----------------
static void run_step(int first,
                     const float* cur_obj, const float* cur_pred,
                     const __half* curObjH, const __half* curPredH,
                     float* next_obj, float* next_pred,
                     __half* nextObjH, __half* nextPredH,   // null on last step
                     const int* pidx,
                     const float* w_e2v, const float* b_e2v,
                     const float* w_v2e, const float* b_v2e,
                     const float* b_ih, const float* b_hh,
                     float* aO1, float* aO2, float* pP1, float* pP2,
                     float* msgO, __half* msgO_h, __half* msgP_h,
                     __half* objH_out, __half* predH_out,   // written by rs_f2h when first
                     const __half* Wih_h, const __half* Whh_h)
{
    if (first) {
        // float inputs: compute scalars + produce half copies (single read pass)
        rs_f2h_kernel<<<(N_OBJ * 32 + 255) / 256, 256>>>(cur_obj, N_OBJ, w_e2v, w_v2e + DD,
                                                         aO1, aO2, objH_out);
        rs_f2h_kernel<<<(N_PAIR * 32 + 255) / 256, 256>>>(cur_pred, N_PAIR, w_e2v + DD, w_v2e,
                                                          pP1, pP2, predH_out);
    } else {
        // half copies already exist (written by step-0 GRU): scalars only
        rs_half_kernel<<<(N_OBJ * 32 + 255) / 256, 256>>>(curObjH, N_OBJ, w_e2v, w_v2e + DD,
                                                          aO1, aO2);
        rs_half_kernel<<<(N_PAIR * 32 + 255) / 256, 256>>>(curPredH, N_PAIR, w_e2v + DD, w_v2e,
                                                           pP1, pP2);
    }
    zero_kernel<<<(N_OBJ * DD / 4 + 255) / 256, 256>>>((float4*)msgO, N_OBJ * DD / 4);
    edge_kernel<<<(N_PAIR * 32 + 255) / 256, 256>>>(cur_pred, cur_obj, pidx,
                                                    aO1, aO2, pP1, pP2,
                                                    b_e2v, b_v2e, msgO, msgP_h);
    f2h_kernel<<<(N_OBJ * DD / 8 + 255) / 256, 256>>>(msgO, msgO_h, N_OBJ * DD / 8);
    gru_fp16<<<dim3(DD / TBN, N_OBJ / TBM), 256, GRU_SMEM>>>(
        msgO_h, curObjH, Wih_h, Whh_h, b_ih, b_hh, next_obj, nextObjH);
    gru_fp16<<<dim3(DD / TBN, N_PAIR / TBM), 256, GRU_SMEM>>>(
        msgP_h, curPredH, Wih_h, Whh_h, b_ih, b_hh, next_pred, nextPredH);
}

extern "C" void kernel_launch(void* const* d_in, const int* in_sizes, int n_in,
                              void* d_out, int out_size)
{
    (void)in_sizes; (void)n_in; (void)out_size;
    const float* x_obj  = (const float*)d_in[0];
    const float* x_pred = (const float*)d_in[1];
    const int*   pidx   = (const int*)d_in[2];
    const float* w_e2v  = (const float*)d_in[3];
    const float* b_e2v  = (const float*)d_in[4];
    const float* w_v2e  = (const float*)d_in[5];
    const float* b_v2e  = (const float*)d_in[6];
    const float* w_ih   = (const float*)d_in[7];
    const float* w_hh   = (const float*)d_in[8];
    const float* b_ih   = (const float*)d_in[9];
    const float* b_hh   = (const float*)d_in[10];
    float* out = (float*)d_out;

    cudaFuncSetAttribute(gru_fp16, cudaFuncAttributeMaxDynamicSharedMemorySize, GRU_SMEM);

    float *objA, *predA, *msgO, *aO1, *aO2, *pP1, *pP2;
    __half *msgP_h, *msgO_h, *objH_h, *predH_h, *objB_h, *predB_h, *Wih_h, *Whh_h;
    cudaGetSymbolAddress((void**)&objA,    g_objA);
    cudaGetSymbolAddress((void**)&predA,   g_predA);
    cudaGetSymbolAddress((void**)&msgO,    g_msgO);
    cudaGetSymbolAddress((void**)&aO1,     g_aO1);
    cudaGetSymbolAddress((void**)&aO2,     g_aO2);
    cudaGetSymbolAddress((void**)&pP1,     g_pP1);
    cudaGetSymbolAddress((void**)&pP2,     g_pP2);
    cudaGetSymbolAddress((void**)&msgP_h,  g_msgP_h);
    cudaGetSymbolAddress((void**)&msgO_h,  g_msgO_h);
    cudaGetSymbolAddress((void**)&objH_h,  g_objH_h);
    cudaGetSymbolAddress((void**)&predH_h, g_predH_h);
    cudaGetSymbolAddress((void**)&objB_h,  g_objB_h);
    cudaGetSymbolAddress((void**)&predB_h, g_predB_h);
    cudaGetSymbolAddress((void**)&Wih_h,   g_Wih_h);
    cudaGetSymbolAddress((void**)&Whh_h,   g_Whh_h);

    // weight conversion (deterministic every call)
    f2h_kernel<<<(3 * DD * DD / 8 + 255) / 256, 256>>>(w_ih, Wih_h, 3 * DD * DD / 8);
    f2h_kernel<<<(3 * DD * DD / 8 + 255) / 256, 256>>>(w_hh, Whh_h, 3 * DD * DD / 8);

    float* out_obj  = out;
    float* out_pred = out + (size_t)N_OBJ * DD;

    // step 0: float inputs -> float scratch + half copies (dual-write GRU)
    run_step(1, x_obj, x_pred, objH_h, predH_h,
             objA, predA, objB_h, predB_h,
             pidx, w_e2v, b_e2v, w_v2e, b_v2e, b_ih, b_hh,
             aO1, aO2, pP1, pP2, msgO, msgO_h, msgP_h,
             objH_h, predH_h, Wih_h, Whh_h);
    // step 1: scalars from half copies; output float only
    run_step(0, objA, predA, objB_h, predB_h,
             out_obj, out_pred, (__half*)0, (__half*)0,
             pidx, w_e2v, b_e2v, w_v2e, b_v2e, b_ih, b_hh,
             aO1, aO2, pP1, pP2, msgO, msgO_h, msgP_h,
             objH_h, predH_h, Wih_h, Whh_h);
}

// round 16
// speedup vs baseline: 1.1158x; 1.0052x over previous
#include <cuda_runtime.h>
#include <cuda_fp16.h>
#include <math.h>
#include <stdint.h>

#define N_OBJ  16384
#define N_PAIR 131072
#define DD     256

// ---------------- scratch (static device memory; no allocations) ----------------
__device__ float g_objA[(size_t)N_OBJ  * DD];   // float intermediates after step 0
__device__ float g_predA[(size_t)N_PAIR * DD];
__device__ float g_msgO[(size_t)N_OBJ  * DD];
__device__ float g_aO1[N_OBJ];
__device__ float g_aO2[N_OBJ];
__device__ float g_pP1[N_PAIR];
__device__ float g_pP2[N_PAIR];
// half-precision MMA operand buffers
__device__ __half g_msgP_h[(size_t)N_PAIR * DD];
__device__ __half g_msgO_h[(size_t)N_OBJ  * DD];
__device__ __half g_objH_h[(size_t)N_OBJ  * DD];   // half(x_obj)  (step-0 H operand)
__device__ __half g_predH_h[(size_t)N_PAIR * DD];  // half(x_pred)
__device__ __half g_objB_h[(size_t)N_OBJ  * DD];   // half(objA)   (step-1 H operand)
__device__ __half g_predB_h[(size_t)N_PAIR * DD];  // half(predA)
__device__ __half g_Wih_h[3 * DD * DD];
__device__ __half g_Whh_h[3 * DD * DD];

__device__ __forceinline__ float sigf(float x) { return 1.0f / (1.0f + expf(-x)); }

// ---------------- float -> half conversion (8 elems / thread) ----------------
__global__ void f2h_kernel(const float* __restrict__ src, __half* __restrict__ dst, int n8)
{
    int i = blockIdx.x * blockDim.x + threadIdx.x;
    if (i >= n8) return;
    const float4* s4 = (const float4*)src;
    float4 a = s4[2 * i];
    float4 b = s4[2 * i + 1];
    __half2 h[4];
    h[0] = __floats2half2_rn(a.x, a.y);
    h[1] = __floats2half2_rn(a.z, a.w);
    h[2] = __floats2half2_rn(b.x, b.y);
    h[3] = __floats2half2_rn(b.z, b.w);
    ((uint4*)dst)[i] = *(uint4*)h;
}

// ---------------- rs bodies (device helpers) ----------------
__device__ __forceinline__ void rs_f32_body(const float* __restrict__ X, int row, int lane,
                                            const float* __restrict__ wA,
                                            const float* __restrict__ wB,
                                            float* __restrict__ outA, float* __restrict__ outB,
                                            __half* __restrict__ Xh)
{
    const float4* xr = (const float4*)(X + (size_t)row * DD);
    const float4* wa4 = (const float4*)wA;
    const float4* wb4 = (const float4*)wB;
    float sA = 0.f, sB = 0.f;
    __half2 hout[4];
#pragma unroll
    for (int h = 0; h < 2; ++h) {
        int c4 = 2 * lane + h;
        float4 v = xr[c4];
        float4 a = wa4[c4];
        float4 b = wb4[c4];
        float rx = fmaxf(v.x, 0.f), ry = fmaxf(v.y, 0.f);
        float rz = fmaxf(v.z, 0.f), rw = fmaxf(v.w, 0.f);
        sA += rx * a.x + ry * a.y + rz * a.z + rw * a.w;
        sB += rx * b.x + ry * b.y + rz * b.z + rw * b.w;
        hout[2 * h]     = __floats2half2_rn(v.x, v.y);
        hout[2 * h + 1] = __floats2half2_rn(v.z, v.w);
    }
    ((uint4*)(Xh + (size_t)row * DD))[lane] = *(uint4*)hout;
#pragma unroll
    for (int o = 16; o > 0; o >>= 1) {
        sA += __shfl_xor_sync(0xFFFFFFFFu, sA, o);
        sB += __shfl_xor_sync(0xFFFFFFFFu, sB, o);
    }
    if (lane == 0) { outA[row] = sA; outB[row] = sB; }
}

__device__ __forceinline__ void rs_f16_body(const __half* __restrict__ X, int row, int lane,
                                            const float* __restrict__ wA,
                                            const float* __restrict__ wB,
                                            float* __restrict__ outA, float* __restrict__ outB)
{
    uint4 v = ((const uint4*)(X + (size_t)row * DD))[lane];   // 8 halves
    const __half2* vh = (const __half2*)&v;
    const float4* wa4 = (const float4*)wA;
    const float4* wb4 = (const float4*)wB;
    float4 a0 = wa4[2 * lane], a1 = wa4[2 * lane + 1];
    float4 b0 = wb4[2 * lane], b1 = wb4[2 * lane + 1];
    float aw[8] = {a0.x, a0.y, a0.z, a0.w, a1.x, a1.y, a1.z, a1.w};
    float bw[8] = {b0.x, b0.y, b0.z, b0.w, b1.x, b1.y, b1.z, b1.w};
    float sA = 0.f, sB = 0.f;
#pragma unroll
    for (int q = 0; q < 4; ++q) {
        float2 f = __half22float2(vh[q]);
        float r0 = fmaxf(f.x, 0.f), r1 = fmaxf(f.y, 0.f);
        sA += r0 * aw[2 * q] + r1 * aw[2 * q + 1];
        sB += r0 * bw[2 * q] + r1 * bw[2 * q + 1];
    }
#pragma unroll
    for (int o = 16; o > 0; o >>= 1) {
        sA += __shfl_xor_sync(0xFFFFFFFFu, sA, o);
        sB += __shfl_xor_sync(0xFFFFFFFFu, sB, o);
    }
    if (lane == 0) { outA[row] = sA; outB[row] = sB; }
}

// ---------------- merged prep kernels: rs(pred) + rs(obj) + zero(msgO) ----------
// Grid segments: [0, 4096) pred rs ; [4096, 4608) obj rs ; [4608, 5120) zero.
#define PRED_RSB (N_PAIR / 8)               // 4096 (8 rows per 256-thr block)
#define OBJ_RSB  (N_OBJ / 8)                // 2048? no: N_OBJ/8 = 2048 -- careful
// N_OBJ = 16384 rows / 8 rows-per-block = 2048 blocks
#define ZERO_B   512                         // 512 * 256 * 8 float4 = 1M float4 = N_OBJ*DD/4
#define PREP_GRID (PRED_RSB + OBJ_RSB + ZERO_B)

__global__ void prep_f32(const float* __restrict__ xo, const float* __restrict__ xp,
                         const float* __restrict__ w_e2v, const float* __restrict__ w_v2e,
                         float* __restrict__ aO1, float* __restrict__ aO2,
                         float* __restrict__ pP1, float* __restrict__ pP2,
                         __half* __restrict__ objH, __half* __restrict__ predH,
                         float4* __restrict__ msgO4)
{
    int b = blockIdx.x;
    int warp = threadIdx.x >> 5;
    int lane = threadIdx.x & 31;
    if (b < PRED_RSB) {
        int row = b * 8 + warp;
        rs_f32_body(xp, row, lane, w_e2v + DD, w_v2e, pP1, pP2, predH);
    } else if (b < PRED_RSB + OBJ_RSB) {
        int row = (b - PRED_RSB) * 8 + warp;
        rs_f32_body(xo, row, lane, w_e2v, w_v2e + DD, aO1, aO2, objH);
    } else {
        int zb = b - PRED_RSB - OBJ_RSB;
        int base = zb * 2048 + threadIdx.x;
#pragma unroll
        for (int i = 0; i < 8; ++i)
            msgO4[base + i * 256] = make_float4(0.f, 0.f, 0.f, 0.f);
    }
}

__global__ void prep_f16(const __half* __restrict__ xoH, const __half* __restrict__ xpH,
                         const float* __restrict__ w_e2v, const float* __restrict__ w_v2e,
                         float* __restrict__ aO1, float* __restrict__ aO2,
                         float* __restrict__ pP1, float* __restrict__ pP2,
                         float4* __restrict__ msgO4)
{
    int b = blockIdx.x;
    int warp = threadIdx.x >> 5;
    int lane = threadIdx.x & 31;
    if (b < PRED_RSB) {
        int row = b * 8 + warp;
        rs_f16_body(xpH, row, lane, w_e2v + DD, w_v2e, pP1, pP2);
    } else if (b < PRED_RSB + OBJ_RSB) {
        int row = (b - PRED_RSB) * 8 + warp;
        rs_f16_body(xoH, row, lane, w_e2v, w_v2e + DD, aO1, aO2);
    } else {
        int zb = b - PRED_RSB - OBJ_RSB;
        int base = zb * 2048 + threadIdx.x;
#pragma unroll
        for (int i = 0; i < 8; ++i)
            msgO4[base + i * 256] = make_float4(0.f, 0.f, 0.f, 0.f);
    }
}

// ---------------- edge kernel (R12 float version; msgP half out) ----------------
__global__ void edge_kernel(const float* __restrict__ xp,
                            const float* __restrict__ xo,
                            const int*   __restrict__ pidx,
                            const float* __restrict__ aO1, const float* __restrict__ aO2,
                            const float* __restrict__ pP1, const float* __restrict__ pP2,
                            const float* __restrict__ b_e2v, const float* __restrict__ b_v2e,
                            float* __restrict__ msgO, __half* __restrict__ msgP)
{
    int e = (blockIdx.x * blockDim.x + threadIdx.x) >> 5;
    int lane = threadIdx.x & 31;
    if (e >= N_PAIR) return;

    int s = pidx[2 * e];
    int o = pidx[2 * e + 1];
    float be = b_e2v[0];
    float bv = b_v2e[0];
    float p1 = pP1[e], p2 = pP2[e];
    float g1 = sigf(aO1[s] + p1 + be);
    float g2 = sigf(aO1[o] + p1 + be);
    float gs = sigf(aO2[s] + p2 + bv);
    float go = sigf(aO2[o] + p2 + bv);

    const float4* xpr = (const float4*)(xp + (size_t)e * DD);
    const float4* xsr = (const float4*)(xo + (size_t)s * DD);
    const float4* xor4 = (const float4*)(xo + (size_t)o * DD);
    __half2* mp = (__half2*)(msgP + (size_t)e * DD);
    float4* mos = (float4*)(msgO + (size_t)s * DD);
    float4* moo = (float4*)(msgO + (size_t)o * DD);

#pragma unroll
    for (int h = 0; h < 2; ++h) {
        int c = lane + h * 32;
        float4 vp = xpr[c];
        float4 vs = xsr[c];
        float4 vo = xor4[c];

        float ox = gs * vs.x + go * vo.x;
        float oy = gs * vs.y + go * vo.y;
        float oz = gs * vs.z + go * vo.z;
        float ow = gs * vs.w + go * vo.w;
        mp[2 * c]     = __floats2half2_rn(ox, oy);
        mp[2 * c + 1] = __floats2half2_rn(oz, ow);

        float4 as = make_float4(g1 * vp.x, g1 * vp.y, g1 * vp.z, g1 * vp.w);
        float4 ao = make_float4(g2 * vp.x, g2 * vp.y, g2 * vp.z, g2 * vp.w);
        atomicAdd(&mos[c], as);
        atomicAdd(&moo[c], ao);
    }
}

// ================= fp16 mma.sync fused GRU — merged obj+pred launch ============
#define TBM 128
#define TBN 32
#define TBK 32            // halves per stage
#define ROWB 80           // smem row stride bytes (40 halves)
#define NBUF 3
#define NPB (N_PAIR / TBM)   // 1024 pred row-blocks (first in grid.y)
#define NOB (N_OBJ / TBM)    // 128 obj row-blocks (appended)

#define ABUF (TBM * ROWB)            // 10240 B per matrix per buffer
#define BGT  (TBN * ROWB)            // 2560 B per gate tile
#define BBUF (6 * BGT)               // 15360 B per buffer
#define OFF_AX 0
#define OFF_AH (NBUF * ABUF)         // 30720
#define OFF_B  (2 * NBUF * ABUF)     // 61440
#define GRU_SMEM (OFF_B + NBUF * BBUF)  // 107520

__device__ __forceinline__ uint32_t smem_u32(const void* p) {
    return (uint32_t)__cvta_generic_to_shared(p);
}
#define CP16(dst, src) \
    asm volatile("cp.async.cg.shared.global [%0], [%1], 16;\n" :: "r"(dst), "l"(src) : "memory")
__device__ __forceinline__ void cp_commit() {
    asm volatile("cp.async.commit_group;\n" ::: "memory");
}
template<int N> __device__ __forceinline__ void cp_wait() {
    asm volatile("cp.async.wait_group %0;\n" :: "n"(N) : "memory");
}
__device__ __forceinline__ void ldsm4(uint32_t* r, uint32_t addr) {
    asm volatile("ldmatrix.sync.aligned.m8n8.x4.shared.b16 {%0,%1,%2,%3}, [%4];\n"
        : "=r"(r[0]), "=r"(r[1]), "=r"(r[2]), "=r"(r[3]) : "r"(addr));
}
__device__ __forceinline__ void mma_f16(float* c, const uint32_t* a, const uint32_t* b) {
    asm volatile("mma.sync.aligned.m16n8k16.row.col.f32.f16.f16.f32 "
        "{%0,%1,%2,%3}, {%4,%5,%6,%7}, {%8,%9}, {%0,%1,%2,%3};\n"
        : "+f"(c[0]), "+f"(c[1]), "+f"(c[2]), "+f"(c[3])
        : "r"(a[0]), "r"(a[1]), "r"(a[2]), "r"(a[3]), "r"(b[0]), "r"(b[1]));
}

__global__ __launch_bounds__(256, 2)
void gru_fp16(const __half* __restrict__ XhP, const __half* __restrict__ HhP,
              float* __restrict__ YP, __half* __restrict__ YhP,
              const __half* __restrict__ XhO, const __half* __restrict__ HhO,
              float* __restrict__ YO, __half* __restrict__ YhO,
              const __half* __restrict__ Wih, const __half* __restrict__ Whh,
              const float* __restrict__ bih, const float* __restrict__ bhh)
{
    extern __shared__ __align__(128) char smem[];
    const uint32_t sb = smem_u32(smem);

    const int tid  = threadIdx.x;
    const int lane = tid & 31;
    const int w    = tid >> 5;
    const int wm   = w >> 1;     // 0..3
    const int wn   = w & 1;      // 0..1
    const int by   = blockIdx.y;
    const int bn   = blockIdx.x;  // d-block == k-stage index holding our H cols
    const int d0   = bn * TBN;

    // segment select: pred blocks first, obj blocks appended
    const __half* Xh; const __half* Hh; float* Y; __half* Yh; int m0;
    if (by < NPB) { Xh = XhP; Hh = HhP; Y = YP; Yh = YhP; m0 = by * TBM; }
    else          { Xh = XhO; Hh = HhO; Y = YO; Yh = YhO; m0 = (by - NPB) * TBM; }

    float acc[4][2][2][4] = {};  // [gate][mi][ni][reg]
    float2 hval[2][2][2];        // [ni][mi][p]

    const int NSTAGE = DD / TBK;  // 8

    auto stage = [&](int kc, int buf) {
        const int k0 = kc * TBK;
#pragma unroll
        for (int j = 0; j < 2; ++j) {
            int slot = tid + 256 * j;       // 0..511
            int row = slot >> 2;            // 0..127
            int c   = slot & 3;             // 16B chunk (8 halves)
            uint32_t dx = sb + OFF_AX + buf * ABUF + row * ROWB + c * 16;
            CP16(dx, Xh + (size_t)(m0 + row) * DD + k0 + c * 8);
            uint32_t dh = sb + OFF_AH + buf * ABUF + row * ROWB + c * 16;
            CP16(dh, Hh + (size_t)(m0 + row) * DD + k0 + c * 8);
        }
#pragma unroll
        for (int j = 0; j < 3; ++j) {
            int slot = tid + 256 * j;       // 0..767
            int g = slot >> 7;              // 0..5
            int r = (slot >> 2) & 31;
            int c = slot & 3;
            const __half* W = (g < 3) ? Wih : Whh;
            int grow = (g % 3) * DD + d0 + r;
            uint32_t db = sb + OFF_B + buf * BBUF + g * BGT + r * ROWB + c * 16;
            CP16(db, W + (size_t)grow * DD + k0 + c * 8);
        }
    };

    stage(0, 0); cp_commit();
    stage(1, 1); cp_commit();

    const int rowA  = lane & 15;
    const int colAh = (lane >> 4) * 16;
    const int rowB  = (lane & 7) + ((lane >> 4) * 8);
    const int colBh = ((lane >> 3) & 1) * 16;

#pragma unroll 1
    for (int kc = 0; kc < NSTAGE; ++kc) {
        int buf = kc % NBUF;
        if (kc + 2 < NSTAGE) {
            stage(kc + 2, (kc + 2) % NBUF);
            cp_commit();
            cp_wait<2>();
        } else if (kc + 1 < NSTAGE) {
            cp_wait<1>();
        } else {
            cp_wait<0>();
        }
        __syncthreads();

        if (kc == bn) {
            const char* hb = smem + OFF_AH + buf * ABUF;
#pragma unroll
            for (int ni = 0; ni < 2; ++ni)
#pragma unroll
            for (int mi = 0; mi < 2; ++mi)
#pragma unroll
            for (int p = 0; p < 2; ++p) {
                int mr = wm * 32 + mi * 16 + (lane >> 2) + p * 8;
                int cc = wn * 16 + ni * 8 + (lane & 3) * 2;
                __half2 hh = *(const __half2*)(hb + mr * ROWB + cc * 2);
                hval[ni][mi][p] = __half22float2(hh);
            }
        }

        const uint32_t aXb = sb + OFF_AX + buf * ABUF;
        const uint32_t aHb = sb + OFF_AH + buf * ABUF;
        const uint32_t bb  = sb + OFF_B  + buf * BBUF;

#pragma unroll
        for (int c = 0; c < 2; ++c) {
            uint32_t aX[2][4], aH[2][4], bf[6][4];
#pragma unroll
            for (int mi = 0; mi < 2; ++mi) {
                uint32_t ra = (wm * 32 + mi * 16 + rowA) * ROWB + c * 32 + colAh;
                ldsm4(aX[mi], aXb + ra);
                ldsm4(aH[mi], aHb + ra);
            }
#pragma unroll
            for (int g = 0; g < 6; ++g) {
                uint32_t rb = g * BGT + (wn * 16 + rowB) * ROWB + c * 32 + colBh;
                ldsm4(bf[g], bb + rb);
            }
#pragma unroll
            for (int mi = 0; mi < 2; ++mi)
#pragma unroll
            for (int ni = 0; ni < 2; ++ni) {
                mma_f16(acc[0][mi][ni], aX[mi], &bf[0][2 * ni]);  // r: X@Wr_ih
                mma_f16(acc[0][mi][ni], aH[mi], &bf[3][2 * ni]);  // r: H@Wr_hh
                mma_f16(acc[1][mi][ni], aX[mi], &bf[1][2 * ni]);  // z: X@Wz_ih
                mma_f16(acc[1][mi][ni], aH[mi], &bf[4][2 * ni]);  // z: H@Wz_hh
                mma_f16(acc[2][mi][ni], aX[mi], &bf[2][2 * ni]);  // i_n
                mma_f16(acc[3][mi][ni], aH[mi], &bf[5][2 * ni]);  // h_n
            }
        }
        __syncthreads();
    }

    // ---- fused GRU epilogue (H blend from registers; optional half output) ----
    const int mwarp = m0 + wm * 32;
    const int dwarp = d0 + wn * 16;
#pragma unroll
    for (int ni = 0; ni < 2; ++ni) {
        const int dA = dwarp + ni * 8 + (lane & 3) * 2;
        const float brA = __ldg(bih + dA)          + __ldg(bhh + dA);
        const float brB = __ldg(bih + dA + 1)      + __ldg(bhh + dA + 1);
        const float bzA = __ldg(bih + DD + dA)     + __ldg(bhh + DD + dA);
        const float bzB = __ldg(bih + DD + dA + 1) + __ldg(bhh + DD + dA + 1);
        const float biA = __ldg(bih + 2 * DD + dA);
        const float biB = __ldg(bih + 2 * DD + dA + 1);
        const float bnA = __ldg(bhh + 2 * DD + dA);
        const float bnB = __ldg(bhh + 2 * DD + dA + 1);
#pragma unroll
        for (int mi = 0; mi < 2; ++mi) {
#pragma unroll
            for (int p = 0; p < 2; ++p) {
                const int m = mwarp + mi * 16 + (lane >> 2) + p * 8;
                const float cr0 = acc[0][mi][ni][2 * p], cr1 = acc[0][mi][ni][2 * p + 1];
                const float cz0 = acc[1][mi][ni][2 * p], cz1 = acc[1][mi][ni][2 * p + 1];
                const float ci0 = acc[2][mi][ni][2 * p], ci1 = acc[2][mi][ni][2 * p + 1];
                const float cn0 = acc[3][mi][ni][2 * p], cn1 = acc[3][mi][ni][2 * p + 1];
                const float2 h2 = hval[ni][mi][p];
                const float r0 = sigf(cr0 + brA);
                const float r1 = sigf(cr1 + brB);
                const float z0 = sigf(cz0 + bzA);
                const float z1 = sigf(cz1 + bzB);
                const float n0 = tanhf(ci0 + biA + r0 * (cn0 + bnA));
                const float n1 = tanhf(ci1 + biB + r1 * (cn1 + bnB));
                float2 y2;
                y2.x = (1.0f - z0) * n0 + z0 * h2.x;
                y2.y = (1.0f - z1) * n1 + z1 * h2.y;
                *(float2*)(Y + (size_t)m * DD + dA) = y2;
                if (Yh) {
                    *(__half2*)(Yh + (size_t)m * DD + dA) = __floats2half2_rn(y2.x, y2.y);
                }
            }
        }
    }
}

extern "C" void kernel_launch(void* const* d_in, const int* in_sizes, int n_in,
                              void* d_out, int out_size)
{
    (void)in_sizes; (void)n_in; (void)out_size;
    const float* x_obj  = (const float*)d_in[0];
    const float* x_pred = (const float*)d_in[1];
    const int*   pidx   = (const int*)d_in[2];
    const float* w_e2v  = (const float*)d_in[3];
    const float* b_e2v  = (const float*)d_in[4];
    const float* w_v2e  = (const float*)d_in[5];
    const float* b_v2e  = (const float*)d_in[6];
    const float* w_ih   = (const float*)d_in[7];
    const float* w_hh   = (const float*)d_in[8];
    const float* b_ih   = (const float*)d_in[9];
    const float* b_hh   = (const float*)d_in[10];
    float* out = (float*)d_out;

    cudaFuncSetAttribute(gru_fp16, cudaFuncAttributeMaxDynamicSharedMemorySize, GRU_SMEM);

    float *objA, *predA, *msgO, *aO1, *aO2, *pP1, *pP2;
    __half *msgP_h, *msgO_h, *objH_h, *predH_h, *objB_h, *predB_h, *Wih_h, *Whh_h;
    cudaGetSymbolAddress((void**)&objA,    g_objA);
    cudaGetSymbolAddress((void**)&predA,   g_predA);
    cudaGetSymbolAddress((void**)&msgO,    g_msgO);
    cudaGetSymbolAddress((void**)&aO1,     g_aO1);
    cudaGetSymbolAddress((void**)&aO2,     g_aO2);
    cudaGetSymbolAddress((void**)&pP1,     g_pP1);
    cudaGetSymbolAddress((void**)&pP2,     g_pP2);
    cudaGetSymbolAddress((void**)&msgP_h,  g_msgP_h);
    cudaGetSymbolAddress((void**)&msgO_h,  g_msgO_h);
    cudaGetSymbolAddress((void**)&objH_h,  g_objH_h);
    cudaGetSymbolAddress((void**)&predH_h, g_predH_h);
    cudaGetSymbolAddress((void**)&objB_h,  g_objB_h);
    cudaGetSymbolAddress((void**)&predB_h, g_predB_h);
    cudaGetSymbolAddress((void**)&Wih_h,   g_Wih_h);
    cudaGetSymbolAddress((void**)&Whh_h,   g_Whh_h);

    // weight conversion (deterministic every call)
    f2h_kernel<<<(3 * DD * DD / 8 + 255) / 256, 256>>>(w_ih, Wih_h, 3 * DD * DD / 8);
    f2h_kernel<<<(3 * DD * DD / 8 + 255) / 256, 256>>>(w_hh, Whh_h, 3 * DD * DD / 8);

    float* out_obj  = out;
    float* out_pred = out + (size_t)N_OBJ * DD;

    // ---------------- step 0 ----------------
    // prep: rs(pred)+rs(obj)+zero(msgO) in one launch; produces half copies too
    prep_f32<<<PREP_GRID, 256>>>(x_obj, x_pred, w_e2v, w_v2e,
                                 aO1, aO2, pP1, pP2, objH_h, predH_h, (float4*)msgO);
    edge_kernel<<<(N_PAIR * 32 + 255) / 256, 256>>>(x_pred, x_obj, pidx,
                                                    aO1, aO2, pP1, pP2,
                                                    b_e2v, b_v2e, msgO, msgP_h);
    f2h_kernel<<<(N_OBJ * DD / 8 + 255) / 256, 256>>>(msgO, msgO_h, N_OBJ * DD / 8);
    gru_fp16<<<dim3(DD / TBN, NPB + NOB), 256, GRU_SMEM>>>(
        msgP_h, predH_h, predA, predB_h,     // pred segment (first 1024 row-blocks)
        msgO_h, objH_h, objA, objB_h,        // obj segment (last 128 row-blocks)
        Wih_h, Whh_h, b_ih, b_hh);

    // ---------------- step 1 ----------------
    prep_f16<<<PREP_GRID, 256>>>(objB_h, predB_h, w_e2v, w_v2e,
                                 aO1, aO2, pP1, pP2, (float4*)msgO);
    edge_kernel<<<(N_PAIR * 32 + 255) / 256, 256>>>(predA, objA, pidx,
                                                    aO1, aO2, pP1, pP2,
                                                    b_e2v, b_v2e, msgO, msgP_h);
    f2h_kernel<<<(N_OBJ * DD / 8 + 255) / 256, 256>>>(msgO, msgO_h, N_OBJ * DD / 8);
    gru_fp16<<<dim3(DD / TBN, NPB + NOB), 256, GRU_SMEM>>>(
        msgP_h, predB_h, out_pred, (__half*)0,
        msgO_h, objB_h, out_obj, (__half*)0,
        Wih_h, Whh_h, b_ih, b_hh);
}